// round 14
// baseline (speedup 1.0000x reference)
#include <cuda_runtime.h>
#include <cstddef>
#include <cstdint>

// Hin2vec layer: B=262144, N=1e6, R=64, H=128.
// R14: cp.async (LDGSTS.cg) deep-pipelined gather engine. Gather rows go
// L2 -> smem directly (bypassing the L1tex MSHR in-flight cap that pinned
// all LDG variants at ~60% DRAM). Per-warp 3-stage ring, 4 elems/stage,
// lane j copies & reads its own 16B slice -> no intra-warp barriers.

#define H_DIM 128
#define R_DIM 64
#define WPB   4      // warps per block
#define S     3      // pipeline stages per warp
#define EPS   4      // elements per stage
#define ROWS  (2 * EPS)   // 8 gather rows per stage
#define NBLOCKS (148 * 4)

__device__ float d_reWr[R_DIM * H_DIM];   // 32 KB: s*(1-s) of clamp(Wr)

__global__ void hin_prep(const float* __restrict__ Wr, float* __restrict__ loss_ptr) {
    const int t = blockIdx.x * blockDim.x + threadIdx.x;
    if (t < R_DIM * H_DIM) {
        float e = fminf(fmaxf(Wr[t], -6.0f), 6.0f);
        float s = 1.0f / (1.0f + __expf(-e));
        d_reWr[t] = s * (1.0f - s);
    }
    if (t == 0 && loss_ptr) *loss_ptr = 0.0f;
}

__device__ __forceinline__ void cp16(float4* smem_dst, const float4* gsrc, bool pred) {
    unsigned saddr = (unsigned)__cvta_generic_to_shared(smem_dst);
    asm volatile(
        "{\n\t"
        ".reg .pred p;\n\t"
        "setp.ne.b32 p, %0, 0;\n\t"
        "@p cp.async.cg.shared.global [%1], [%2], 16;\n\t"
        "}"
        :: "r"((int)pred), "r"(saddr), "l"(gsrc));
}

__device__ __forceinline__ float dot_rw(float4 a, float4 b, float4 w) {
    float acc = a.x * b.x * w.x;
    acc = fmaf(a.y * b.y, w.y, acc);
    acc = fmaf(a.z * b.z, w.z, acc);
    acc = fmaf(a.w * b.w, w.w, acc);
    return acc;
}

__global__ void __launch_bounds__(WPB * 32)
hin_main(const int* __restrict__ x,
         const int* __restrict__ y,
         const int* __restrict__ r,
         const int* __restrict__ l,
         const float4* __restrict__ Wx,   // [N, H/4]
         float* __restrict__ out,         // [B, 2] logits
         float* __restrict__ loss_out,    // scalar (may be null)
         int B, float invB)
{
    // [warp][stage][row][lane] : 4*3*8*32*16B = 49152 B (full 48KB static)
    __shared__ float4 ring[WPB][S][ROWS][32];

    const int wid    = threadIdx.x >> 5;
    const int lane   = threadIdx.x & 31;
    const int nwarps = gridDim.x * WPB;
    const int nchunk = B >> 2;                 // B % 4 == 0

    float loss_acc = 0.0f;

    int issue_chunk = blockIdx.x * WPB + wid;  // next chunk to ISSUE
    int comp_chunk  = issue_chunk;             // next chunk to COMPUTE

    // idx for the chunk about to be issued
    int4 xv = make_int4(0,0,0,0), yv = xv;
    if (issue_chunk < nchunk) {
        xv = *(const int4*)(x + issue_chunk * EPS);
        yv = *(const int4*)(y + issue_chunk * EPS);
    }

    // ---- prologue: fill S stages ----
    #pragma unroll
    for (int s = 0; s < S; s++) {
        const bool v = (issue_chunk < nchunk);
        float4* slot = &ring[wid][s][0][lane];       // row stride = 32 float4
        cp16(slot + 0*32, Wx + (unsigned)xv.x * 32 + lane, v);
        cp16(slot + 1*32, Wx + (unsigned)xv.y * 32 + lane, v);
        cp16(slot + 2*32, Wx + (unsigned)xv.z * 32 + lane, v);
        cp16(slot + 3*32, Wx + (unsigned)xv.w * 32 + lane, v);
        cp16(slot + 4*32, Wx + (unsigned)yv.x * 32 + lane, v);
        cp16(slot + 5*32, Wx + (unsigned)yv.y * 32 + lane, v);
        cp16(slot + 6*32, Wx + (unsigned)yv.z * 32 + lane, v);
        cp16(slot + 7*32, Wx + (unsigned)yv.w * 32 + lane, v);
        asm volatile("cp.async.commit_group;");
        issue_chunk += nwarps;
        if (issue_chunk < nchunk) {
            xv = *(const int4*)(x + issue_chunk * EPS);
            yv = *(const int4*)(y + issue_chunk * EPS);
        }
    }

    // ---- main loop ----
    int slot_i = 0;
    while (comp_chunk < nchunk) {
        // oldest stage's copies complete (per-thread ordering, own bytes only)
        asm volatile("cp.async.wait_group %0;" :: "n"(S - 1));

        const int base = comp_chunk * EPS;

        // regularization rows (hot 32KB L1 table) — overlaps with LDS below
        const int4 rv = *(const int4*)(r + base);
        const float4* RW = (const float4*)d_reWr;
        const float4 rw0 = __ldg(RW + (unsigned)rv.x * 32 + lane);
        const float4 rw1 = __ldg(RW + (unsigned)rv.y * 32 + lane);
        const float4 rw2 = __ldg(RW + (unsigned)rv.z * 32 + lane);
        const float4 rw3 = __ldg(RW + (unsigned)rv.w * 32 + lane);

        const float4* slot = &ring[wid][slot_i][0][lane];
        const float4 ax0 = slot[0*32];
        const float4 ax1 = slot[1*32];
        const float4 ax2 = slot[2*32];
        const float4 ax3 = slot[3*32];
        const float4 ay0 = slot[4*32];
        const float4 ay1 = slot[5*32];
        const float4 ay2 = slot[6*32];
        const float4 ay3 = slot[7*32];

        float a0 = dot_rw(ax0, ay0, rw0);
        float a1 = dot_rw(ax1, ay1, rw1);
        float a2 = dot_rw(ax2, ay2, rw2);
        float a3 = dot_rw(ax3, ay3, rw3);

        // refill this slot with stage comp+S (before the reduce, so the
        // copies overlap the shuffle/epilogue tail)
        {
            const bool v = (issue_chunk < nchunk);
            float4* wslot = &ring[wid][slot_i][0][lane];
            cp16(wslot + 0*32, Wx + (unsigned)xv.x * 32 + lane, v);
            cp16(wslot + 1*32, Wx + (unsigned)xv.y * 32 + lane, v);
            cp16(wslot + 2*32, Wx + (unsigned)xv.z * 32 + lane, v);
            cp16(wslot + 3*32, Wx + (unsigned)xv.w * 32 + lane, v);
            cp16(wslot + 4*32, Wx + (unsigned)yv.x * 32 + lane, v);
            cp16(wslot + 5*32, Wx + (unsigned)yv.y * 32 + lane, v);
            cp16(wslot + 6*32, Wx + (unsigned)yv.z * 32 + lane, v);
            cp16(wslot + 7*32, Wx + (unsigned)yv.w * 32 + lane, v);
            asm volatile("cp.async.commit_group;");
            issue_chunk += nwarps;
            if (issue_chunk < nchunk) {
                xv = *(const int4*)(x + issue_chunk * EPS);
                yv = *(const int4*)(y + issue_chunk * EPS);
            }
        }

        // four interleaved butterfly reductions
        #pragma unroll
        for (int o = 16; o > 0; o >>= 1) {
            a0 += __shfl_xor_sync(0xFFFFFFFFu, a0, o);
            a1 += __shfl_xor_sync(0xFFFFFFFFu, a1, o);
            a2 += __shfl_xor_sync(0xFFFFFFFFu, a2, o);
            a3 += __shfl_xor_sync(0xFFFFFFFFu, a3, o);
        }

        if (lane < EPS) {
            const float acc = (lane == 0) ? a0 : (lane == 1) ? a1 : (lane == 2) ? a2 : a3;
            const float p = 1.0f / (1.0f + __expf(-acc));

            float2 lg;
            lg.x = p;
            lg.y = 1.0f - p;
            reinterpret_cast<float2*>(out)[base + lane] = lg;

            if (loss_out) {
                const float ea  = __expf(p);
                const float eb  = __expf(1.0f - p);
                const float lse = __logf(ea + eb);
                const int   li  = __ldg(l + base + lane);
                const float chosen = (li == 0) ? p : (1.0f - p);
                loss_acc += (lse - chosen) * invB;
            }
        }

        comp_chunk += nwarps;
        slot_i = (slot_i + 1 == S) ? 0 : slot_i + 1;
    }

    if (loss_out) {
        // drain all pending copies before reusing ring as scratch
        asm volatile("cp.async.wait_group 0;");
        loss_acc += __shfl_xor_sync(0xFFFFFFFFu, loss_acc, 1);
        loss_acc += __shfl_xor_sync(0xFFFFFFFFu, loss_acc, 2);
        if (lane == 0) ring[wid][0][0][0].x = loss_acc;   // own warp's area
        __syncthreads();
        if (threadIdx.x == 0) {
            float ssum = 0.0f;
            #pragma unroll
            for (int w = 0; w < WPB; w++) ssum += ring[w][0][0][0].x;
            atomicAdd(loss_out, ssum);
        }
    }
}

extern "C" void kernel_launch(void* const* d_in, const int* in_sizes, int n_in,
                              void* d_out, int out_size)
{
    const int*    x  = (const int*)d_in[0];
    const int*    y  = (const int*)d_in[1];
    const int*    r  = (const int*)d_in[2];
    const int*    l  = (const int*)d_in[3];
    const float4* Wx = (const float4*)d_in[4];
    const float*  Wr = (const float*)d_in[5];

    const int B = in_sizes[0];
    float* out = (float*)d_out;
    float* loss_ptr = (out_size > 2 * B) ? (out + 2 * B) : nullptr;

    hin_prep<<<(R_DIM * H_DIM + 255) / 256, 256>>>(Wr, loss_ptr);

    hin_main<<<NBLOCKS, WPB * 32>>>(
        x, y, r, l, Wx, out, loss_ptr, B, 1.0f / (float)B);
}